// round 4
// baseline (speedup 1.0000x reference)
#include <cuda_runtime.h>
#include <cuda_bf16.h>
#include <math.h>
#include <stdint.h>

// Problem constants
#define BATCH 4
#define SEQ   2048
#define DMODEL 1024
#define NHEAD 8
#define HDIM  128
#define MROWS (BATCH*SEQ)          // 8192
#define NTOT  (MROWS*DMODEL)       // 8388608
#define SOFTMAX_SCALE 0.03125f     // 1/sqrt(1024)

// ---------------------------------------------------------------------------
// Scratch (device globals: allocation-free rule)
// ---------------------------------------------------------------------------
__device__ float g_Qn[NTOT];
__device__ float g_Kn[NTOT];
__device__ float g_Vr[NTOT];
__device__ float g_q[NTOT];
__device__ float g_k[NTOT];
__device__ float g_v[NTOT];
__device__ float g_O[NTOT];
__device__ float g_OlnR[NTOT];
__device__ float g_OlnF[NTOT];
__device__ float g_Wr[4 * DMODEL * DMODEL];

// ---------------------------------------------------------------------------
// PTX helpers
// ---------------------------------------------------------------------------
__device__ __forceinline__ float tf32r(float x)
{
    unsigned o;
    asm("cvt.rna.tf32.f32 %0, %1;" : "=r"(o) : "f"(x));
    return __uint_as_float(o);
}

__device__ __forceinline__ void cpa16(float* dst, const float* src)
{
    unsigned d = (unsigned)__cvta_generic_to_shared(dst);
    asm volatile("cp.async.ca.shared.global [%0], [%1], 16;" :: "r"(d), "l"(src));
}
#define CP_COMMIT() asm volatile("cp.async.commit_group;")
#define CP_WAIT0()  asm volatile("cp.async.wait_group 0;")
#define CP_WAIT1()  asm volatile("cp.async.wait_group 1;")

__device__ __forceinline__ void ldsm4(unsigned (&r)[4], const float* p)
{
    unsigned addr = (unsigned)__cvta_generic_to_shared(p);
    asm volatile("ldmatrix.sync.aligned.m8n8.x4.shared.b16 {%0,%1,%2,%3}, [%4];"
                 : "=r"(r[0]), "=r"(r[1]), "=r"(r[2]), "=r"(r[3]) : "r"(addr));
}

__device__ __forceinline__ void ldsm2(unsigned (&r)[2], const float* p)
{
    unsigned addr = (unsigned)__cvta_generic_to_shared(p);
    asm volatile("ldmatrix.sync.aligned.m8n8.x2.shared.b16 {%0,%1}, [%2];"
                 : "=r"(r[0]), "=r"(r[1]) : "r"(addr));
}

__device__ __forceinline__ void mma_tf32(float (&d)[4], const unsigned (&a)[4],
                                         const unsigned (&b)[2])
{
    asm volatile(
        "mma.sync.aligned.m16n8k8.row.col.f32.tf32.tf32.f32 "
        "{%0,%1,%2,%3}, {%4,%5,%6,%7}, {%8,%9}, {%0,%1,%2,%3};"
        : "+f"(d[0]), "+f"(d[1]), "+f"(d[2]), "+f"(d[3])
        : "r"(a[0]), "r"(a[1]), "r"(a[2]), "r"(a[3]), "r"(b[0]), "r"(b[1]));
}

// ---------------------------------------------------------------------------
// Elementwise tf32 rounding
// ---------------------------------------------------------------------------
__global__ __launch_bounds__(256) void round_tf32(const float* __restrict__ x,
                                                  float* __restrict__ y, int n4)
{
    const int i = blockIdx.x * 256 + threadIdx.x;
    if (i < n4) {
        float4 v = ((const float4*)x)[i];
        float4 o;
        o.x = tf32r(v.x); o.y = tf32r(v.y);
        o.z = tf32r(v.z); o.w = tf32r(v.w);
        ((float4*)y)[i] = o;
    }
}

// ---------------------------------------------------------------------------
// LayerNorm (D=1024). y = tf32-rounded; y2 (DUAL) = full fp32.
// ---------------------------------------------------------------------------
template <bool DUAL>
__global__ __launch_bounds__(256) void ln_kernel(const float* __restrict__ x,
                                                 const float* __restrict__ g,
                                                 const float* __restrict__ bta,
                                                 float* __restrict__ y,
                                                 float* __restrict__ y2)
{
    const size_t row = blockIdx.x;
    const int tid = threadIdx.x;
    float4 v = ((const float4*)(x + row * DMODEL))[tid];
    float s  = v.x + v.y + v.z + v.w;
    float ss = fmaf(v.x, v.x, fmaf(v.y, v.y, fmaf(v.z, v.z, v.w * v.w)));
#pragma unroll
    for (int o = 16; o > 0; o >>= 1) {
        s  += __shfl_xor_sync(0xffffffffu, s,  o);
        ss += __shfl_xor_sync(0xffffffffu, ss, o);
    }
    __shared__ float sb[8], ssb[8];
    if ((tid & 31) == 0) { sb[tid >> 5] = s; ssb[tid >> 5] = ss; }
    __syncthreads();
    s = 0.f; ss = 0.f;
#pragma unroll
    for (int i = 0; i < 8; i++) { s += sb[i]; ss += ssb[i]; }
    const float mean = s * (1.0f / DMODEL);
    const float var  = ss * (1.0f / DMODEL) - mean * mean;
    const float rstd = rsqrtf(var + 1e-5f);
    float4 gg = ((const float4*)g)[tid];
    float4 bb = ((const float4*)bta)[tid];
    float4 o;
    o.x = (v.x - mean) * rstd * gg.x + bb.x;
    o.y = (v.y - mean) * rstd * gg.y + bb.y;
    o.z = (v.z - mean) * rstd * gg.z + bb.z;
    o.w = (v.w - mean) * rstd * gg.w + bb.w;
    if (DUAL) ((float4*)(y2 + row * DMODEL))[tid] = o;
    float4 r;
    r.x = tf32r(o.x); r.y = tf32r(o.y); r.z = tf32r(o.z); r.w = tf32r(o.w);
    ((float4*)(y + row * DMODEL))[tid] = r;
}

// ---------------------------------------------------------------------------
// TF32 GEMM, 3-stage cp.async pipeline, one barrier per k-iter.
// 128x128x32 tile, 8 warps (2M x 4N). Batched over gridDim.z (up to 3 ops).
// EPI: C = R + gelu_exact(A@B).  ROUND: tf32-round C on store.
// ---------------------------------------------------------------------------
__device__ __forceinline__ float gelu_exact(float x)
{
    return 0.5f * x * (1.0f + erff(x * 0.70710678118654752440f));
}

#define AS_STRIDE 36
#define BS_STRIDE 136
#define G_ABUF (128 * AS_STRIDE)   // 4608 floats
#define G_BBUF (32 * BS_STRIDE)    // 4352 floats
#define G_STAGE (G_ABUF + G_BBUF)  // 8960 floats
#define G_SMEM_BYTES (3 * G_STAGE * 4)   // 107520

struct GemmBatch {
    const float* A[3];
    const float* B[3];
    float*       C[3];
    const float* R[3];
};

template <bool EPI, bool ROUND>
__global__ __launch_bounds__(256, 2) void gemm_tf32(GemmBatch gb, int M, int N, int K)
{
    extern __shared__ float sm[];

    const float* __restrict__ A  = gb.A[blockIdx.z];
    const float* __restrict__ Bm = gb.B[blockIdx.z];
    float* __restrict__ C        = gb.C[blockIdx.z];
    const float* __restrict__ R  = gb.R[blockIdx.z];

    const int tid  = threadIdx.x;
    const int lane = tid & 31;
    const int wid  = tid >> 5;
    const int grp  = lane >> 2;
    const int tig  = lane & 3;
    const int wm   = wid & 1;
    const int wn   = wid >> 1;
    const int bx   = blockIdx.x * 128;
    const int by   = blockIdx.y * 128;

    const int a_row = lane & 15;
    const int a_col = (lane >> 4) << 2;

    const int lar = tid >> 3;
    const int lac = (tid & 7) << 2;
    const int lbr = tid >> 5;
    const int lbc = (tid & 31) << 2;

    float acc[4][4][4];
#pragma unroll
    for (int mt = 0; mt < 4; mt++)
#pragma unroll
        for (int nt = 0; nt < 4; nt++)
#pragma unroll
            for (int c = 0; c < 4; c++) acc[mt][nt][c] = 0.f;

    const int nk = K >> 5;

    // prologue: tiles 0 and 1
#pragma unroll
    for (int p = 0; p < 2; p++) {
        float* As = sm + p * G_STAGE;
        float* Bs = As + G_ABUF;
        const int k0 = p << 5;
#pragma unroll
        for (int i = 0; i < 4; i++) {
            const int r = lar + i * 32;
            cpa16(&As[r * AS_STRIDE + lac], &A[(size_t)(by + r) * K + k0 + lac]);
        }
#pragma unroll
        for (int i = 0; i < 4; i++) {
            const int r = lbr + i * 8;
            cpa16(&Bs[r * BS_STRIDE + lbc], &Bm[(size_t)(k0 + r) * N + bx + lbc]);
        }
        CP_COMMIT();
    }

    int stage = 0;
    for (int t = 0; t < nk; t++) {
        if (t + 1 < nk) { CP_WAIT1(); } else { CP_WAIT0(); }
        __syncthreads();

        // prefetch tile t+2 into the stage freed at iter t-1
        if (t + 2 < nk) {
            const int ps = (stage + 2) % 3;
            float* As = sm + ps * G_STAGE;
            float* Bs = As + G_ABUF;
            const int k0 = (t + 2) << 5;
#pragma unroll
            for (int i = 0; i < 4; i++) {
                const int r = lar + i * 32;
                cpa16(&As[r * AS_STRIDE + lac], &A[(size_t)(by + r) * K + k0 + lac]);
            }
#pragma unroll
            for (int i = 0; i < 4; i++) {
                const int r = lbr + i * 8;
                cpa16(&Bs[r * BS_STRIDE + lbc], &Bm[(size_t)(k0 + r) * N + bx + lbc]);
            }
            CP_COMMIT();
        }

        const float* Ab = sm + stage * G_STAGE;
        const float* Bb = Ab + G_ABUF;
#pragma unroll
        for (int ks = 0; ks < 4; ks++) {
            unsigned af[4][4];
#pragma unroll
            for (int mt = 0; mt < 4; mt++)
                ldsm4(af[mt], &Ab[(wm * 64 + mt * 16 + a_row) * AS_STRIDE + ks * 8 + a_col]);
            unsigned bf[4][2];
#pragma unroll
            for (int nt = 0; nt < 4; nt++) {
                const int nc = wn * 32 + nt * 8 + grp;
                bf[nt][0] = __float_as_uint(Bb[(ks * 8 + tig)     * BS_STRIDE + nc]);
                bf[nt][1] = __float_as_uint(Bb[(ks * 8 + tig + 4) * BS_STRIDE + nc]);
            }
#pragma unroll
            for (int mt = 0; mt < 4; mt++)
#pragma unroll
                for (int nt = 0; nt < 4; nt++)
                    mma_tf32(acc[mt][nt], af[mt], bf[nt]);
        }
        stage = (stage + 1) % 3;
    }

    // epilogue
#pragma unroll
    for (int mt = 0; mt < 4; mt++) {
        const int r0 = by + wm * 64 + mt * 16 + grp;
#pragma unroll
        for (int nt = 0; nt < 4; nt++) {
            const int c0 = bx + wn * 32 + nt * 8 + tig * 2;
            const size_t i0 = (size_t)r0 * N + c0;
            const size_t i1 = (size_t)(r0 + 8) * N + c0;
            float2 o0 = make_float2(acc[mt][nt][0], acc[mt][nt][1]);
            float2 o1 = make_float2(acc[mt][nt][2], acc[mt][nt][3]);
            if (EPI) {
                float2 r0v = *(const float2*)&R[i0];
                float2 r1v = *(const float2*)&R[i1];
                o0.x = r0v.x + gelu_exact(o0.x);
                o0.y = r0v.y + gelu_exact(o0.y);
                o1.x = r1v.x + gelu_exact(o1.x);
                o1.y = r1v.y + gelu_exact(o1.y);
            }
            if (ROUND) {
                o0.x = tf32r(o0.x); o0.y = tf32r(o0.y);
                o1.x = tf32r(o1.x); o1.y = tf32r(o1.y);
            }
            *(float2*)&C[i0] = o0;
            *(float2*)&C[i1] = o1;
        }
    }
}

// ---------------------------------------------------------------------------
// Flash attention, TF32. BM=128, BN=64, HD=128. 8 warps, warp-local softmax.
// Pipelined: K double-buffered (prefetched during PV/S of prior tile),
// V single-buffered (issued right after prior PV, lands during S+softmax).
// smem: Q 67.6K + K 2x33.8K + V 34.8K + P 34.8K = 204.8KB, 1 CTA/SM.
// ---------------------------------------------------------------------------
#define FA_QS 132
#define FA_KS 132
#define FA_VS 136
#define FA_PS 68
#define FA_KBUF (64 * FA_KS)
#define FA_Q_OFF 0
#define FA_K_OFF (128 * FA_QS)
#define FA_V_OFF (FA_K_OFF + 2 * FA_KBUF)
#define FA_P_OFF (FA_V_OFF + 64 * FA_VS)
#define FA_SMEM_FLOATS (FA_P_OFF + 128 * FA_PS)
#define FA_SMEM_BYTES  (FA_SMEM_FLOATS * 4)   // 204800

__global__ __launch_bounds__(256, 1) void flash_tc(const float* __restrict__ qg,
                                                   const float* __restrict__ kg,
                                                   const float* __restrict__ vg,
                                                   float* __restrict__ og)
{
    extern __shared__ float sm[];
    float* Qs = sm + FA_Q_OFF;
    float* Ks = sm + FA_K_OFF;   // [2][64][132]
    float* Vs = sm + FA_V_OFF;   // [64][136]
    float* Ps = sm + FA_P_OFF;   // [128][68]

    const int bh = blockIdx.y;
    const int b  = bh >> 3;
    const int h  = bh & 7;
    const int m0 = blockIdx.x * 128;
    const int tid  = threadIdx.x;
    const int lane = tid & 31;
    const int wid  = tid >> 5;
    const int grp  = lane >> 2;
    const int tig  = lane & 3;

    const int a_row = lane & 15;
    const int a_col = (lane >> 4) << 2;
    const int b_row = lane & 7;
    const int b_col = ((lane >> 3) & 1) << 2;

    const size_t base = (size_t)b * SEQ * DMODEL + (size_t)h * HDIM;
    const float* qb = qg + base;
    const float* kb = kg + base;
    const float* vb = vg + base;

    const int ldr = tid >> 5;
    const int ldc = (tid & 31) << 2;

    // group 0: Q + K(0)
    {
#pragma unroll
        for (int i = 0; i < 16; i++)
            cpa16(&Qs[(ldr + i * 8) * FA_QS + ldc], &qb[(size_t)(m0 + ldr + i * 8) * DMODEL + ldc]);
#pragma unroll
        for (int i = 0; i < 8; i++)
            cpa16(&Ks[(ldr + i * 8) * FA_KS + ldc], &kb[(size_t)(ldr + i * 8) * DMODEL + ldc]);
        CP_COMMIT();
    }
    // group 1: V(0)
    {
#pragma unroll
        for (int i = 0; i < 8; i++)
            cpa16(&Vs[(ldr + i * 8) * FA_VS + ldc], &vb[(size_t)(ldr + i * 8) * DMODEL + ldc]);
        CP_COMMIT();
    }

    float mi[2] = {-1e30f, -1e30f};
    float li[2] = {0.f, 0.f};
    float oacc[16][4];
#pragma unroll
    for (int nt = 0; nt < 16; nt++)
#pragma unroll
        for (int c = 0; c < 4; c++) oacc[nt][c] = 0.f;

    const int NT = SEQ / 64;
    for (int t = 0; t < NT; t++) {
        const float* Kb = Ks + (t & 1) * FA_KBUF;

        // K(t) (+Q at t=0) arrived: one group may remain pending (V(t))
        CP_WAIT1();
        __syncthreads();

        // prefetch K(t+1) into the other K buffer (readers finished at t-1)
        if (t + 1 < NT) {
            float* Kn = Ks + ((t + 1) & 1) * FA_KBUF;
            const size_t j1 = (size_t)(t + 1) * 64;
#pragma unroll
            for (int i = 0; i < 8; i++)
                cpa16(&Kn[(ldr + i * 8) * FA_KS + ldc], &kb[(j1 + ldr + i * 8) * DMODEL + ldc]);
            CP_COMMIT();
        }

        // ---- S = Q K^T : warp tile 16x64, K-dim 128 ----
        float s[8][4];
#pragma unroll
        for (int nt = 0; nt < 8; nt++)
#pragma unroll
            for (int c = 0; c < 4; c++) s[nt][c] = 0.f;

#pragma unroll
        for (int ks = 0; ks < 16; ks++) {
            unsigned af[4];
            ldsm4(af, &Qs[(wid * 16 + a_row) * FA_QS + ks * 8 + a_col]);
#pragma unroll
            for (int nt = 0; nt < 8; nt++) {
                unsigned bf[2];
                ldsm2(bf, &Kb[(nt * 8 + b_row) * FA_KS + ks * 8 + b_col]);
                mma_tf32(s[nt], af, bf);
            }
        }

        // ---- warp-local online softmax ----
        float mx0 = -1e30f, mx1 = -1e30f;
#pragma unroll
        for (int nt = 0; nt < 8; nt++) {
#pragma unroll
            for (int c = 0; c < 4; c++) {
                float x = s[nt][c] * SOFTMAX_SCALE;
                x = fminf(fmaxf(x, -10000.f), 10000.f);
                s[nt][c] = x;
            }
            mx0 = fmaxf(mx0, fmaxf(s[nt][0], s[nt][1]));
            mx1 = fmaxf(mx1, fmaxf(s[nt][2], s[nt][3]));
        }
        mx0 = fmaxf(mx0, __shfl_xor_sync(0xffffffffu, mx0, 1));
        mx0 = fmaxf(mx0, __shfl_xor_sync(0xffffffffu, mx0, 2));
        mx1 = fmaxf(mx1, __shfl_xor_sync(0xffffffffu, mx1, 1));
        mx1 = fmaxf(mx1, __shfl_xor_sync(0xffffffffu, mx1, 2));
        const float mn0 = fmaxf(mi[0], mx0);
        const float mn1 = fmaxf(mi[1], mx1);
        const float al0 = __expf(mi[0] - mn0);
        const float al1 = __expf(mi[1] - mn1);
        mi[0] = mn0; mi[1] = mn1;

        float sum0 = 0.f, sum1 = 0.f;
        const int prow = wid * 16 + grp;
#pragma unroll
        for (int nt = 0; nt < 8; nt++) {
            const float p0 = __expf(s[nt][0] - mn0);
            const float p1 = __expf(s[nt][1] - mn0);
            const float p2 = __expf(s[nt][2] - mn1);
            const float p3 = __expf(s[nt][3] - mn1);
            sum0 += p0 + p1;
            sum1 += p2 + p3;
            const int col = nt * 8 + tig * 2;
            *(float2*)&Ps[prow * FA_PS + col]       = make_float2(tf32r(p0), tf32r(p1));
            *(float2*)&Ps[(prow + 8) * FA_PS + col] = make_float2(tf32r(p2), tf32r(p3));
        }
        sum0 += __shfl_xor_sync(0xffffffffu, sum0, 1);
        sum0 += __shfl_xor_sync(0xffffffffu, sum0, 2);
        sum1 += __shfl_xor_sync(0xffffffffu, sum1, 1);
        sum1 += __shfl_xor_sync(0xffffffffu, sum1, 2);
        li[0] = li[0] * al0 + sum0;
        li[1] = li[1] * al1 + sum1;

#pragma unroll
        for (int nt = 0; nt < 16; nt++) {
            oacc[nt][0] *= al0; oacc[nt][1] *= al0;
            oacc[nt][2] *= al1; oacc[nt][3] *= al1;
        }

        // V(t) arrived (K(t+1) group may stay pending)
        CP_WAIT1();
        __syncthreads();

        // ---- O += P V : warp tile 16x128, K-dim 64 ----
#pragma unroll
        for (int ks = 0; ks < 8; ks++) {
            unsigned af[4];
            ldsm4(af, &Ps[(wid * 16 + a_row) * FA_PS + ks * 8 + a_col]);
#pragma unroll
            for (int nt = 0; nt < 16; nt++) {
                unsigned bf[2];
                const int nc = nt * 8 + grp;
                bf[0] = __float_as_uint(Vs[(ks * 8 + tig)     * FA_VS + nc]);
                bf[1] = __float_as_uint(Vs[(ks * 8 + tig + 4) * FA_VS + nc]);
                mma_tf32(oacc[nt], af, bf);
            }
        }

        // all reads of V(t) done -> issue V(t+1)
        __syncthreads();
        if (t + 1 < NT) {
            const size_t j1 = (size_t)(t + 1) * 64;
#pragma unroll
            for (int i = 0; i < 8; i++)
                cpa16(&Vs[(ldr + i * 8) * FA_VS + ldc], &vb[(j1 + ldr + i * 8) * DMODEL + ldc]);
            CP_COMMIT();
        }
    }

    // write O
    const float i0 = 1.0f / li[0];
    const float i1 = 1.0f / li[1];
    const size_t row0 = (size_t)(b * SEQ + m0 + wid * 16 + grp);
#pragma unroll
    for (int nt = 0; nt < 16; nt++) {
        const int col = h * HDIM + nt * 8 + tig * 2;
        *(float2*)&og[row0 * DMODEL + col]       = make_float2(oacc[nt][0] * i0, oacc[nt][1] * i0);
        *(float2*)&og[(row0 + 8) * DMODEL + col] = make_float2(oacc[nt][2] * i1, oacc[nt][3] * i1);
    }
}

// ---------------------------------------------------------------------------
// Launch
// ---------------------------------------------------------------------------
extern "C" void kernel_launch(void* const* d_in, const int* in_sizes, int n_in,
                              void* d_out, int out_size)
{
    const float* Q     = (const float*)d_in[0];
    const float* Kin   = (const float*)d_in[1];
    const float* Vin   = (const float*)d_in[2];
    const float* Wq    = (const float*)d_in[3];
    const float* Wk    = (const float*)d_in[4];
    const float* Wv    = (const float*)d_in[5];
    const float* Wo    = (const float*)d_in[6];
    const float* pre_g = (const float*)d_in[7];
    const float* pre_b = (const float*)d_in[8];
    const float* ln_g  = (const float*)d_in[9];
    const float* ln_b  = (const float*)d_in[10];
    float* out = (float*)d_out;

    float *qn, *kn, *vr, *qq, *kk, *vv, *oo, *olnR, *olnF, *wr;
    cudaGetSymbolAddress((void**)&qn,   g_Qn);
    cudaGetSymbolAddress((void**)&kn,   g_Kn);
    cudaGetSymbolAddress((void**)&vr,   g_Vr);
    cudaGetSymbolAddress((void**)&qq,   g_q);
    cudaGetSymbolAddress((void**)&kk,   g_k);
    cudaGetSymbolAddress((void**)&vv,   g_v);
    cudaGetSymbolAddress((void**)&oo,   g_O);
    cudaGetSymbolAddress((void**)&olnR, g_OlnR);
    cudaGetSymbolAddress((void**)&olnF, g_OlnF);
    cudaGetSymbolAddress((void**)&wr,   g_Wr);

    cudaFuncSetAttribute(flash_tc,
                         cudaFuncAttributeMaxDynamicSharedMemorySize, FA_SMEM_BYTES);
    cudaFuncSetAttribute(gemm_tf32<false, true>,
                         cudaFuncAttributeMaxDynamicSharedMemorySize, G_SMEM_BYTES);
    cudaFuncSetAttribute(gemm_tf32<true, false>,
                         cudaFuncAttributeMaxDynamicSharedMemorySize, G_SMEM_BYTES);

    const int WN4 = DMODEL * DMODEL / 4;
    float* wq = wr;
    float* wk = wr + DMODEL * DMODEL;
    float* wv = wr + 2 * DMODEL * DMODEL;
    float* wo = wr + 3 * DMODEL * DMODEL;

    // 0) pre-round weights + V input to tf32
    round_tf32<<<WN4 / 256, 256>>>(Wq, wq, WN4);
    round_tf32<<<WN4 / 256, 256>>>(Wk, wk, WN4);
    round_tf32<<<WN4 / 256, 256>>>(Wv, wv, WN4);
    round_tf32<<<WN4 / 256, 256>>>(Wo, wo, WN4);
    round_tf32<<<NTOT / 4 / 256, 256>>>(Vin, vr, NTOT / 4);

    // 1) pre-LN on Q and K
    ln_kernel<false><<<MROWS, 256>>>(Q,   pre_g, pre_b, qn, nullptr);
    ln_kernel<false><<<MROWS, 256>>>(Kin, pre_g, pre_b, kn, nullptr);

    // 2) projections — single batched launch (gridDim.z = 3)
    {
        GemmBatch gb;
        gb.A[0] = qn;  gb.B[0] = wq; gb.C[0] = qq; gb.R[0] = nullptr;
        gb.A[1] = kn;  gb.B[1] = wk; gb.C[1] = kk; gb.R[1] = nullptr;
        gb.A[2] = vr;  gb.B[2] = wv; gb.C[2] = vv; gb.R[2] = nullptr;
        dim3 gg(DMODEL / 128, MROWS / 128, 3);
        gemm_tf32<false, true><<<gg, 256, G_SMEM_BYTES>>>(gb, MROWS, DMODEL, DMODEL);
    }

    // 3) attention
    flash_tc<<<dim3(SEQ / 128, BATCH * NHEAD), 256, FA_SMEM_BYTES>>>(qq, kk, vv, oo);

    // 4) post-LN (rounded + full)
    ln_kernel<true><<<MROWS, 256>>>(oo, ln_g, ln_b, olnR, olnF);

    // 5) output GEMM + gelu residual
    {
        GemmBatch gb;
        gb.A[0] = olnR; gb.B[0] = wo; gb.C[0] = out; gb.R[0] = olnF;
        gb.A[1] = gb.A[0]; gb.B[1] = gb.B[0]; gb.C[1] = gb.C[0]; gb.R[1] = gb.R[0];
        gb.A[2] = gb.A[0]; gb.B[2] = gb.B[0]; gb.C[2] = gb.C[0]; gb.R[2] = gb.R[0];
        dim3 gg(DMODEL / 128, MROWS / 128, 1);
        gemm_tf32<true, false><<<gg, 256, G_SMEM_BYTES>>>(gb, MROWS, DMODEL, DMODEL);
    }
}

// round 5
// speedup vs baseline: 1.0692x; 1.0692x over previous
#include <cuda_runtime.h>
#include <cuda_bf16.h>
#include <math.h>
#include <stdint.h>

// Problem constants
#define BATCH 4
#define SEQ   2048
#define DMODEL 1024
#define NHEAD 8
#define HDIM  128
#define MROWS (BATCH*SEQ)          // 8192
#define NTOT  (MROWS*DMODEL)       // 8388608
#define SOFTMAX_SCALE 0.03125f     // 1/sqrt(1024)

// ---------------------------------------------------------------------------
// Scratch (device globals: allocation-free rule)
// ---------------------------------------------------------------------------
__device__ float g_Qn[NTOT];
__device__ float g_Kn[NTOT];
__device__ float g_Vr[NTOT];
__device__ float g_q[NTOT];
__device__ float g_k[NTOT];
__device__ float g_v[NTOT];
__device__ float g_O[NTOT];
__device__ float g_OlnR[NTOT];
__device__ float g_OlnF[NTOT];
__device__ float g_Wr[4 * DMODEL * DMODEL];

// ---------------------------------------------------------------------------
// PTX helpers
// ---------------------------------------------------------------------------
__device__ __forceinline__ float tf32r(float x)
{
    unsigned o;
    asm("cvt.rna.tf32.f32 %0, %1;" : "=r"(o) : "f"(x));
    return __uint_as_float(o);
}

__device__ __forceinline__ void cpa16(float* dst, const float* src)
{
    unsigned d = (unsigned)__cvta_generic_to_shared(dst);
    asm volatile("cp.async.ca.shared.global [%0], [%1], 16;" :: "r"(d), "l"(src));
}
#define CP_COMMIT() asm volatile("cp.async.commit_group;")
#define CP_WAIT0()  asm volatile("cp.async.wait_group 0;")
#define CP_WAIT1()  asm volatile("cp.async.wait_group 1;")

__device__ __forceinline__ void ldsm4(unsigned (&r)[4], const float* p)
{
    unsigned addr = (unsigned)__cvta_generic_to_shared(p);
    asm volatile("ldmatrix.sync.aligned.m8n8.x4.shared.b16 {%0,%1,%2,%3}, [%4];"
                 : "=r"(r[0]), "=r"(r[1]), "=r"(r[2]), "=r"(r[3]) : "r"(addr));
}

__device__ __forceinline__ void ldsm2(unsigned (&r)[2], const float* p)
{
    unsigned addr = (unsigned)__cvta_generic_to_shared(p);
    asm volatile("ldmatrix.sync.aligned.m8n8.x2.shared.b16 {%0,%1}, [%2];"
                 : "=r"(r[0]), "=r"(r[1]) : "r"(addr));
}

__device__ __forceinline__ void mma_tf32(float (&d)[4], const unsigned (&a)[4],
                                         const unsigned (&b)[2])
{
    asm volatile(
        "mma.sync.aligned.m16n8k8.row.col.f32.tf32.tf32.f32 "
        "{%0,%1,%2,%3}, {%4,%5,%6,%7}, {%8,%9}, {%0,%1,%2,%3};"
        : "+f"(d[0]), "+f"(d[1]), "+f"(d[2]), "+f"(d[3])
        : "r"(a[0]), "r"(a[1]), "r"(a[2]), "r"(a[3]), "r"(b[0]), "r"(b[1]));
}

// ---------------------------------------------------------------------------
// Fused tf32 rounding for the 4 weight matrices (grid.y selects matrix)
// ---------------------------------------------------------------------------
struct RoundBatch { const float* src[4]; float* dst[4]; };

__global__ __launch_bounds__(256) void round_w4(RoundBatch rb, int n4)
{
    const int i = blockIdx.x * 256 + threadIdx.x;
    const float* __restrict__ x = rb.src[blockIdx.y];
    float* __restrict__ y       = rb.dst[blockIdx.y];
    if (i < n4) {
        float4 v = ((const float4*)x)[i];
        float4 o;
        o.x = tf32r(v.x); o.y = tf32r(v.y);
        o.z = tf32r(v.z); o.w = tf32r(v.w);
        ((float4*)y)[i] = o;
    }
}

__global__ __launch_bounds__(256) void round_tf32(const float* __restrict__ x,
                                                  float* __restrict__ y, int n4)
{
    const int i = blockIdx.x * 256 + threadIdx.x;
    if (i < n4) {
        float4 v = ((const float4*)x)[i];
        float4 o;
        o.x = tf32r(v.x); o.y = tf32r(v.y);
        o.z = tf32r(v.z); o.w = tf32r(v.w);
        ((float4*)y)[i] = o;
    }
}

// ---------------------------------------------------------------------------
// LayerNorm (D=1024). y = tf32-rounded; y2 (DUAL) = full fp32.
// ---------------------------------------------------------------------------
template <bool DUAL>
__global__ __launch_bounds__(256) void ln_kernel(const float* __restrict__ x,
                                                 const float* __restrict__ g,
                                                 const float* __restrict__ bta,
                                                 float* __restrict__ y,
                                                 float* __restrict__ y2)
{
    const size_t row = blockIdx.x;
    const int tid = threadIdx.x;
    float4 v = ((const float4*)(x + row * DMODEL))[tid];
    float s  = v.x + v.y + v.z + v.w;
    float ss = fmaf(v.x, v.x, fmaf(v.y, v.y, fmaf(v.z, v.z, v.w * v.w)));
#pragma unroll
    for (int o = 16; o > 0; o >>= 1) {
        s  += __shfl_xor_sync(0xffffffffu, s,  o);
        ss += __shfl_xor_sync(0xffffffffu, ss, o);
    }
    __shared__ float sb[8], ssb[8];
    if ((tid & 31) == 0) { sb[tid >> 5] = s; ssb[tid >> 5] = ss; }
    __syncthreads();
    s = 0.f; ss = 0.f;
#pragma unroll
    for (int i = 0; i < 8; i++) { s += sb[i]; ss += ssb[i]; }
    const float mean = s * (1.0f / DMODEL);
    const float var  = ss * (1.0f / DMODEL) - mean * mean;
    const float rstd = rsqrtf(var + 1e-5f);
    float4 gg = ((const float4*)g)[tid];
    float4 bb = ((const float4*)bta)[tid];
    float4 o;
    o.x = (v.x - mean) * rstd * gg.x + bb.x;
    o.y = (v.y - mean) * rstd * gg.y + bb.y;
    o.z = (v.z - mean) * rstd * gg.z + bb.z;
    o.w = (v.w - mean) * rstd * gg.w + bb.w;
    if (DUAL) ((float4*)(y2 + row * DMODEL))[tid] = o;
    float4 r;
    r.x = tf32r(o.x); r.y = tf32r(o.y); r.z = tf32r(o.z); r.w = tf32r(o.w);
    ((float4*)(y + row * DMODEL))[tid] = r;
}

// ---------------------------------------------------------------------------
// TF32 GEMM: R3's 2-stage cp.async pipeline (proven), batched over gridDim.z.
// 128x128x32 tile, 8 warps (2M x 4N).
// EPI: C = R + gelu_exact(A@B).  ROUND: tf32-round C on store.
// ---------------------------------------------------------------------------
__device__ __forceinline__ float gelu_exact(float x)
{
    return 0.5f * x * (1.0f + erff(x * 0.70710678118654752440f));
}

#define AS_STRIDE 36
#define BS_STRIDE 136
#define G_ABUF (128 * AS_STRIDE)   // 4608 floats
#define G_BBUF (32 * BS_STRIDE)    // 4352 floats
#define G_SMEM_FLOATS (2 * G_ABUF + 2 * G_BBUF)
#define G_SMEM_BYTES  (G_SMEM_FLOATS * 4)   // 71680

struct GemmBatch {
    const float* A[3];
    const float* B[3];
    float*       C[3];
    const float* R[3];
};

template <bool EPI, bool ROUND>
__global__ __launch_bounds__(256, 2) void gemm_tf32(GemmBatch gb, int M, int N, int K)
{
    extern __shared__ float sm[];
    float* As = sm;                  // [2][128][36]
    float* Bs = sm + 2 * G_ABUF;     // [2][32][136]

    const float* __restrict__ A  = gb.A[blockIdx.z];
    const float* __restrict__ Bm = gb.B[blockIdx.z];
    float* __restrict__ C        = gb.C[blockIdx.z];
    const float* __restrict__ R  = gb.R[blockIdx.z];

    const int tid  = threadIdx.x;
    const int lane = tid & 31;
    const int wid  = tid >> 5;
    const int grp  = lane >> 2;
    const int tig  = lane & 3;
    const int wm   = wid & 1;
    const int wn   = wid >> 1;
    const int bx   = blockIdx.x * 128;
    const int by   = blockIdx.y * 128;

    const int a_row = lane & 15;
    const int a_col = (lane >> 4) << 2;

    const int lar = tid >> 3;
    const int lac = (tid & 7) << 2;
    const int lbr = tid >> 5;
    const int lbc = (tid & 31) << 2;

    float acc[4][4][4];
#pragma unroll
    for (int mt = 0; mt < 4; mt++)
#pragma unroll
        for (int nt = 0; nt < 4; nt++)
#pragma unroll
            for (int c = 0; c < 4; c++) acc[mt][nt][c] = 0.f;

    const int nk = K >> 5;

    // prologue: tile 0
    {
#pragma unroll
        for (int i = 0; i < 4; i++) {
            const int r = lar + i * 32;
            cpa16(&As[r * AS_STRIDE + lac], &A[(size_t)(by + r) * K + lac]);
        }
#pragma unroll
        for (int i = 0; i < 4; i++) {
            const int r = lbr + i * 8;
            cpa16(&Bs[r * BS_STRIDE + lbc], &Bm[(size_t)r * N + bx + lbc]);
        }
        CP_COMMIT();
    }

    for (int t = 0; t < nk; t++) {
        const int cur = t & 1;
        if (t + 1 < nk) {
            const int nxt = cur ^ 1;
            const int k0 = (t + 1) << 5;
#pragma unroll
            for (int i = 0; i < 4; i++) {
                const int r = lar + i * 32;
                cpa16(&As[nxt * G_ABUF + r * AS_STRIDE + lac],
                      &A[(size_t)(by + r) * K + k0 + lac]);
            }
#pragma unroll
            for (int i = 0; i < 4; i++) {
                const int r = lbr + i * 8;
                cpa16(&Bs[nxt * G_BBUF + r * BS_STRIDE + lbc],
                      &Bm[(size_t)(k0 + r) * N + bx + lbc]);
            }
            CP_COMMIT();
            CP_WAIT1();
        } else {
            CP_WAIT0();
        }
        __syncthreads();

        const float* Ab = As + cur * G_ABUF;
        const float* Bb = Bs + cur * G_BBUF;
#pragma unroll
        for (int ks = 0; ks < 4; ks++) {
            unsigned af[4][4];
#pragma unroll
            for (int mt = 0; mt < 4; mt++)
                ldsm4(af[mt], &Ab[(wm * 64 + mt * 16 + a_row) * AS_STRIDE + ks * 8 + a_col]);
            unsigned bf[4][2];
#pragma unroll
            for (int nt = 0; nt < 4; nt++) {
                const int nc = wn * 32 + nt * 8 + grp;
                bf[nt][0] = __float_as_uint(Bb[(ks * 8 + tig)     * BS_STRIDE + nc]);
                bf[nt][1] = __float_as_uint(Bb[(ks * 8 + tig + 4) * BS_STRIDE + nc]);
            }
#pragma unroll
            for (int mt = 0; mt < 4; mt++)
#pragma unroll
                for (int nt = 0; nt < 4; nt++)
                    mma_tf32(acc[mt][nt], af[mt], bf[nt]);
        }
        __syncthreads();
    }

    // epilogue
#pragma unroll
    for (int mt = 0; mt < 4; mt++) {
        const int r0 = by + wm * 64 + mt * 16 + grp;
#pragma unroll
        for (int nt = 0; nt < 4; nt++) {
            const int c0 = bx + wn * 32 + nt * 8 + tig * 2;
            const size_t i0 = (size_t)r0 * N + c0;
            const size_t i1 = (size_t)(r0 + 8) * N + c0;
            float2 o0 = make_float2(acc[mt][nt][0], acc[mt][nt][1]);
            float2 o1 = make_float2(acc[mt][nt][2], acc[mt][nt][3]);
            if (EPI) {
                float2 r0v = *(const float2*)&R[i0];
                float2 r1v = *(const float2*)&R[i1];
                o0.x = r0v.x + gelu_exact(o0.x);
                o0.y = r0v.y + gelu_exact(o0.y);
                o1.x = r1v.x + gelu_exact(o1.x);
                o1.y = r1v.y + gelu_exact(o1.y);
            }
            if (ROUND) {
                o0.x = tf32r(o0.x); o0.y = tf32r(o0.y);
                o1.x = tf32r(o1.x); o1.y = tf32r(o1.y);
            }
            *(float2*)&C[i0] = o0;
            *(float2*)&C[i1] = o1;
        }
    }
}

// ---------------------------------------------------------------------------
// Flash attention, TF32 (R4 pipelined version).
// BM=128, BN=64, HD=128. 8 warps, warp-local softmax.
// K double-buffered (prefetched during S of prior tile), V single-buffered
// (issued right after PV, lands during next S+softmax).
// ---------------------------------------------------------------------------
#define FA_QS 132
#define FA_KS 132
#define FA_VS 136
#define FA_PS 68
#define FA_KBUF (64 * FA_KS)
#define FA_Q_OFF 0
#define FA_K_OFF (128 * FA_QS)
#define FA_V_OFF (FA_K_OFF + 2 * FA_KBUF)
#define FA_P_OFF (FA_V_OFF + 64 * FA_VS)
#define FA_SMEM_FLOATS (FA_P_OFF + 128 * FA_PS)
#define FA_SMEM_BYTES  (FA_SMEM_FLOATS * 4)   // 204800

__global__ __launch_bounds__(256, 1) void flash_tc(const float* __restrict__ qg,
                                                   const float* __restrict__ kg,
                                                   const float* __restrict__ vg,
                                                   float* __restrict__ og)
{
    extern __shared__ float sm[];
    float* Qs = sm + FA_Q_OFF;
    float* Ks = sm + FA_K_OFF;   // [2][64][132]
    float* Vs = sm + FA_V_OFF;   // [64][136]
    float* Ps = sm + FA_P_OFF;   // [128][68]

    const int bh = blockIdx.y;
    const int b  = bh >> 3;
    const int h  = bh & 7;
    const int m0 = blockIdx.x * 128;
    const int tid  = threadIdx.x;
    const int lane = tid & 31;
    const int wid  = tid >> 5;
    const int grp  = lane >> 2;
    const int tig  = lane & 3;

    const int a_row = lane & 15;
    const int a_col = (lane >> 4) << 2;
    const int b_row = lane & 7;
    const int b_col = ((lane >> 3) & 1) << 2;

    const size_t base = (size_t)b * SEQ * DMODEL + (size_t)h * HDIM;
    const float* qb = qg + base;
    const float* kb = kg + base;
    const float* vb = vg + base;

    const int ldr = tid >> 5;
    const int ldc = (tid & 31) << 2;

    // group 0: Q + K(0)
    {
#pragma unroll
        for (int i = 0; i < 16; i++)
            cpa16(&Qs[(ldr + i * 8) * FA_QS + ldc], &qb[(size_t)(m0 + ldr + i * 8) * DMODEL + ldc]);
#pragma unroll
        for (int i = 0; i < 8; i++)
            cpa16(&Ks[(ldr + i * 8) * FA_KS + ldc], &kb[(size_t)(ldr + i * 8) * DMODEL + ldc]);
        CP_COMMIT();
    }
    // group 1: V(0)
    {
#pragma unroll
        for (int i = 0; i < 8; i++)
            cpa16(&Vs[(ldr + i * 8) * FA_VS + ldc], &vb[(size_t)(ldr + i * 8) * DMODEL + ldc]);
        CP_COMMIT();
    }

    float mi[2] = {-1e30f, -1e30f};
    float li[2] = {0.f, 0.f};
    float oacc[16][4];
#pragma unroll
    for (int nt = 0; nt < 16; nt++)
#pragma unroll
        for (int c = 0; c < 4; c++) oacc[nt][c] = 0.f;

    const int NT = SEQ / 64;
    for (int t = 0; t < NT; t++) {
        const float* Kb = Ks + (t & 1) * FA_KBUF;

        // K(t) (+Q at t=0) arrived; V(t) may remain pending
        CP_WAIT1();
        __syncthreads();

        // prefetch K(t+1)
        if (t + 1 < NT) {
            float* Kn = Ks + ((t + 1) & 1) * FA_KBUF;
            const size_t j1 = (size_t)(t + 1) * 64;
#pragma unroll
            for (int i = 0; i < 8; i++)
                cpa16(&Kn[(ldr + i * 8) * FA_KS + ldc], &kb[(j1 + ldr + i * 8) * DMODEL + ldc]);
            CP_COMMIT();
        }

        // ---- S = Q K^T ----
        float s[8][4];
#pragma unroll
        for (int nt = 0; nt < 8; nt++)
#pragma unroll
            for (int c = 0; c < 4; c++) s[nt][c] = 0.f;

#pragma unroll
        for (int ks = 0; ks < 16; ks++) {
            unsigned af[4];
            ldsm4(af, &Qs[(wid * 16 + a_row) * FA_QS + ks * 8 + a_col]);
#pragma unroll
            for (int nt = 0; nt < 8; nt++) {
                unsigned bf[2];
                ldsm2(bf, &Kb[(nt * 8 + b_row) * FA_KS + ks * 8 + b_col]);
                mma_tf32(s[nt], af, bf);
            }
        }

        // ---- warp-local online softmax ----
        float mx0 = -1e30f, mx1 = -1e30f;
#pragma unroll
        for (int nt = 0; nt < 8; nt++) {
#pragma unroll
            for (int c = 0; c < 4; c++) {
                float x = s[nt][c] * SOFTMAX_SCALE;
                x = fminf(fmaxf(x, -10000.f), 10000.f);
                s[nt][c] = x;
            }
            mx0 = fmaxf(mx0, fmaxf(s[nt][0], s[nt][1]));
            mx1 = fmaxf(mx1, fmaxf(s[nt][2], s[nt][3]));
        }
        mx0 = fmaxf(mx0, __shfl_xor_sync(0xffffffffu, mx0, 1));
        mx0 = fmaxf(mx0, __shfl_xor_sync(0xffffffffu, mx0, 2));
        mx1 = fmaxf(mx1, __shfl_xor_sync(0xffffffffu, mx1, 1));
        mx1 = fmaxf(mx1, __shfl_xor_sync(0xffffffffu, mx1, 2));
        const float mn0 = fmaxf(mi[0], mx0);
        const float mn1 = fmaxf(mi[1], mx1);
        const float al0 = __expf(mi[0] - mn0);
        const float al1 = __expf(mi[1] - mn1);
        mi[0] = mn0; mi[1] = mn1;

        float sum0 = 0.f, sum1 = 0.f;
        const int prow = wid * 16 + grp;
#pragma unroll
        for (int nt = 0; nt < 8; nt++) {
            const float p0 = __expf(s[nt][0] - mn0);
            const float p1 = __expf(s[nt][1] - mn0);
            const float p2 = __expf(s[nt][2] - mn1);
            const float p3 = __expf(s[nt][3] - mn1);
            sum0 += p0 + p1;
            sum1 += p2 + p3;
            const int col = nt * 8 + tig * 2;
            *(float2*)&Ps[prow * FA_PS + col]       = make_float2(tf32r(p0), tf32r(p1));
            *(float2*)&Ps[(prow + 8) * FA_PS + col] = make_float2(tf32r(p2), tf32r(p3));
        }
        sum0 += __shfl_xor_sync(0xffffffffu, sum0, 1);
        sum0 += __shfl_xor_sync(0xffffffffu, sum0, 2);
        sum1 += __shfl_xor_sync(0xffffffffu, sum1, 1);
        sum1 += __shfl_xor_sync(0xffffffffu, sum1, 2);
        li[0] = li[0] * al0 + sum0;
        li[1] = li[1] * al1 + sum1;

#pragma unroll
        for (int nt = 0; nt < 16; nt++) {
            oacc[nt][0] *= al0; oacc[nt][1] *= al0;
            oacc[nt][2] *= al1; oacc[nt][3] *= al1;
        }

        // V(t) arrived (K(t+1) group may stay pending)
        CP_WAIT1();
        __syncthreads();

        // ---- O += P V ----
#pragma unroll
        for (int ks = 0; ks < 8; ks++) {
            unsigned af[4];
            ldsm4(af, &Ps[(wid * 16 + a_row) * FA_PS + ks * 8 + a_col]);
#pragma unroll
            for (int nt = 0; nt < 16; nt++) {
                unsigned bf[2];
                const int nc = nt * 8 + grp;
                bf[0] = __float_as_uint(Vs[(ks * 8 + tig)     * FA_VS + nc]);
                bf[1] = __float_as_uint(Vs[(ks * 8 + tig + 4) * FA_VS + nc]);
                mma_tf32(oacc[nt], af, bf);
            }
        }

        // all reads of V(t) done -> issue V(t+1)
        __syncthreads();
        if (t + 1 < NT) {
            const size_t j1 = (size_t)(t + 1) * 64;
#pragma unroll
            for (int i = 0; i < 8; i++)
                cpa16(&Vs[(ldr + i * 8) * FA_VS + ldc], &vb[(j1 + ldr + i * 8) * DMODEL + ldc]);
            CP_COMMIT();
        }
    }

    // write O
    const float i0 = 1.0f / li[0];
    const float i1 = 1.0f / li[1];
    const size_t row0 = (size_t)(b * SEQ + m0 + wid * 16 + grp);
#pragma unroll
    for (int nt = 0; nt < 16; nt++) {
        const int col = h * HDIM + nt * 8 + tig * 2;
        *(float2*)&og[row0 * DMODEL + col]       = make_float2(oacc[nt][0] * i0, oacc[nt][1] * i0);
        *(float2*)&og[(row0 + 8) * DMODEL + col] = make_float2(oacc[nt][2] * i1, oacc[nt][3] * i1);
    }
}

// ---------------------------------------------------------------------------
// Launch
// ---------------------------------------------------------------------------
extern "C" void kernel_launch(void* const* d_in, const int* in_sizes, int n_in,
                              void* d_out, int out_size)
{
    const float* Q     = (const float*)d_in[0];
    const float* Kin   = (const float*)d_in[1];
    const float* Vin   = (const float*)d_in[2];
    const float* Wq    = (const float*)d_in[3];
    const float* Wk    = (const float*)d_in[4];
    const float* Wv    = (const float*)d_in[5];
    const float* Wo    = (const float*)d_in[6];
    const float* pre_g = (const float*)d_in[7];
    const float* pre_b = (const float*)d_in[8];
    const float* ln_g  = (const float*)d_in[9];
    const float* ln_b  = (const float*)d_in[10];
    float* out = (float*)d_out;

    float *qn, *kn, *vr, *qq, *kk, *vv, *oo, *olnR, *olnF, *wr;
    cudaGetSymbolAddress((void**)&qn,   g_Qn);
    cudaGetSymbolAddress((void**)&kn,   g_Kn);
    cudaGetSymbolAddress((void**)&vr,   g_Vr);
    cudaGetSymbolAddress((void**)&qq,   g_q);
    cudaGetSymbolAddress((void**)&kk,   g_k);
    cudaGetSymbolAddress((void**)&vv,   g_v);
    cudaGetSymbolAddress((void**)&oo,   g_O);
    cudaGetSymbolAddress((void**)&olnR, g_OlnR);
    cudaGetSymbolAddress((void**)&olnF, g_OlnF);
    cudaGetSymbolAddress((void**)&wr,   g_Wr);

    cudaFuncSetAttribute(flash_tc,
                         cudaFuncAttributeMaxDynamicSharedMemorySize, FA_SMEM_BYTES);
    cudaFuncSetAttribute(gemm_tf32<false, true>,
                         cudaFuncAttributeMaxDynamicSharedMemorySize, G_SMEM_BYTES);
    cudaFuncSetAttribute(gemm_tf32<true, false>,
                         cudaFuncAttributeMaxDynamicSharedMemorySize, G_SMEM_BYTES);

    const int WN4 = DMODEL * DMODEL / 4;
    float* wq = wr;
    float* wk = wr + DMODEL * DMODEL;
    float* wv = wr + 2 * DMODEL * DMODEL;
    float* wo = wr + 3 * DMODEL * DMODEL;

    // 0) pre-round weights (one fused launch) + V input
    {
        RoundBatch rb;
        rb.src[0] = Wq; rb.dst[0] = wq;
        rb.src[1] = Wk; rb.dst[1] = wk;
        rb.src[2] = Wv; rb.dst[2] = wv;
        rb.src[3] = Wo; rb.dst[3] = wo;
        round_w4<<<dim3(WN4 / 256, 4), 256>>>(rb, WN4);
    }
    round_tf32<<<NTOT / 4 / 256, 256>>>(Vin, vr, NTOT / 4);

    // 1) pre-LN on Q and K
    ln_kernel<false><<<MROWS, 256>>>(Q,   pre_g, pre_b, qn, nullptr);
    ln_kernel<false><<<MROWS, 256>>>(Kin, pre_g, pre_b, kn, nullptr);

    // 2) projections — single batched launch (gridDim.z = 3)
    {
        GemmBatch gb;
        gb.A[0] = qn;  gb.B[0] = wq; gb.C[0] = qq; gb.R[0] = nullptr;
        gb.A[1] = kn;  gb.B[1] = wk; gb.C[1] = kk; gb.R[1] = nullptr;
        gb.A[2] = vr;  gb.B[2] = wv; gb.C[2] = vv; gb.R[2] = nullptr;
        dim3 gg(DMODEL / 128, MROWS / 128, 3);
        gemm_tf32<false, true><<<gg, 256, G_SMEM_BYTES>>>(gb, MROWS, DMODEL, DMODEL);
    }

    // 3) attention
    flash_tc<<<dim3(SEQ / 128, BATCH * NHEAD), 256, FA_SMEM_BYTES>>>(qq, kk, vv, oo);

    // 4) post-LN (rounded + full)
    ln_kernel<true><<<MROWS, 256>>>(oo, ln_g, ln_b, olnR, olnF);

    // 5) output GEMM + gelu residual
    {
        GemmBatch gb;
        gb.A[0] = olnR; gb.B[0] = wo; gb.C[0] = out; gb.R[0] = olnF;
        gb.A[1] = gb.A[0]; gb.B[1] = gb.B[0]; gb.C[1] = gb.C[0]; gb.R[1] = gb.R[0];
        gb.A[2] = gb.A[0]; gb.B[2] = gb.B[0]; gb.C[2] = gb.C[0]; gb.R[2] = gb.R[0];
        dim3 gg(DMODEL / 128, MROWS / 128, 1);
        gemm_tf32<true, false><<<gg, 256, G_SMEM_BYTES>>>(gb, MROWS, DMODEL, DMODEL);
    }
}

// round 6
// speedup vs baseline: 1.1237x; 1.0509x over previous
#include <cuda_runtime.h>
#include <cuda_bf16.h>
#include <math.h>
#include <stdint.h>

// Problem constants
#define BATCH 4
#define SEQ   2048
#define DMODEL 1024
#define NHEAD 8
#define HDIM  128
#define MROWS (BATCH*SEQ)          // 8192
#define NTOT  (MROWS*DMODEL)       // 8388608
#define SOFTMAX_SCALE 0.03125f     // 1/sqrt(1024)

// ---------------------------------------------------------------------------
// Scratch (device globals: allocation-free rule)
// ---------------------------------------------------------------------------
__device__ float g_Qn[NTOT];
__device__ float g_Kn[NTOT];
__device__ float g_Vr[NTOT];
__device__ float g_q[NTOT];
__device__ float g_k[NTOT];
__device__ float g_v[NTOT];
__device__ float g_O[NTOT];
__device__ float g_OlnR[NTOT];
__device__ float g_OlnF[NTOT];
__device__ float g_Wt[4 * DMODEL * DMODEL];   // transposed + rounded weights [N][K]

// ---------------------------------------------------------------------------
// PTX helpers
// ---------------------------------------------------------------------------
__device__ __forceinline__ float tf32r(float x)
{
    unsigned o;
    asm("cvt.rna.tf32.f32 %0, %1;" : "=r"(o) : "f"(x));
    return __uint_as_float(o);
}

__device__ __forceinline__ void cpa16(float* dst, const float* src)
{
    unsigned d = (unsigned)__cvta_generic_to_shared(dst);
    asm volatile("cp.async.ca.shared.global [%0], [%1], 16;" :: "r"(d), "l"(src));
}
#define CP_COMMIT() asm volatile("cp.async.commit_group;")
#define CP_WAIT0()  asm volatile("cp.async.wait_group 0;")
#define CP_WAIT1()  asm volatile("cp.async.wait_group 1;")

__device__ __forceinline__ void ldsm4(unsigned (&r)[4], const float* p)
{
    unsigned addr = (unsigned)__cvta_generic_to_shared(p);
    asm volatile("ldmatrix.sync.aligned.m8n8.x4.shared.b16 {%0,%1,%2,%3}, [%4];"
                 : "=r"(r[0]), "=r"(r[1]), "=r"(r[2]), "=r"(r[3]) : "r"(addr));
}

__device__ __forceinline__ void mma_tf32(float (&d)[4], const unsigned (&a)[4],
                                         unsigned b0, unsigned b1)
{
    asm volatile(
        "mma.sync.aligned.m16n8k8.row.col.f32.tf32.tf32.f32 "
        "{%0,%1,%2,%3}, {%4,%5,%6,%7}, {%8,%9}, {%0,%1,%2,%3};"
        : "+f"(d[0]), "+f"(d[1]), "+f"(d[2]), "+f"(d[3])
        : "r"(a[0]), "r"(a[1]), "r"(a[2]), "r"(a[3]), "r"(b0), "r"(b1));
}

// ---------------------------------------------------------------------------
// Weight transpose + tf32 round: W[K][N] -> Wt[N][K], 4 matrices (grid.z)
// ---------------------------------------------------------------------------
struct WBatch { const float* src[4]; float* dst[4]; };

__global__ __launch_bounds__(256) void transpose_round_w(WBatch wb)
{
    __shared__ float tile[32][33];
    const float* __restrict__ W = wb.src[blockIdx.z];
    float* __restrict__ Wt      = wb.dst[blockIdx.z];
    const int tx = threadIdx.x;   // 0..31
    const int ty = threadIdx.y;   // 0..7
    const int x = blockIdx.x * 32 + tx;          // col (n) of W
#pragma unroll
    for (int j = 0; j < 4; j++) {
        const int y = blockIdx.y * 32 + ty + j * 8;   // row (k) of W
        tile[ty + j * 8][tx] = W[(size_t)y * DMODEL + x];
    }
    __syncthreads();
    const int xo = blockIdx.y * 32 + tx;         // col (k) of Wt
#pragma unroll
    for (int j = 0; j < 4; j++) {
        const int yo = blockIdx.x * 32 + ty + j * 8;  // row (n) of Wt
        Wt[(size_t)yo * DMODEL + xo] = tf32r(tile[tx][ty + j * 8]);
    }
}

__global__ __launch_bounds__(256) void round_tf32(const float* __restrict__ x,
                                                  float* __restrict__ y, int n4)
{
    const int i = blockIdx.x * 256 + threadIdx.x;
    if (i < n4) {
        float4 v = ((const float4*)x)[i];
        float4 o;
        o.x = tf32r(v.x); o.y = tf32r(v.y);
        o.z = tf32r(v.z); o.w = tf32r(v.w);
        ((float4*)y)[i] = o;
    }
}

// ---------------------------------------------------------------------------
// LayerNorm (D=1024). y = tf32-rounded; y2 (DUAL) = full fp32.
// ---------------------------------------------------------------------------
template <bool DUAL>
__global__ __launch_bounds__(256) void ln_kernel(const float* __restrict__ x,
                                                 const float* __restrict__ g,
                                                 const float* __restrict__ bta,
                                                 float* __restrict__ y,
                                                 float* __restrict__ y2)
{
    const size_t row = blockIdx.x;
    const int tid = threadIdx.x;
    float4 v = ((const float4*)(x + row * DMODEL))[tid];
    float s  = v.x + v.y + v.z + v.w;
    float ss = fmaf(v.x, v.x, fmaf(v.y, v.y, fmaf(v.z, v.z, v.w * v.w)));
#pragma unroll
    for (int o = 16; o > 0; o >>= 1) {
        s  += __shfl_xor_sync(0xffffffffu, s,  o);
        ss += __shfl_xor_sync(0xffffffffu, ss, o);
    }
    __shared__ float sb[8], ssb[8];
    if ((tid & 31) == 0) { sb[tid >> 5] = s; ssb[tid >> 5] = ss; }
    __syncthreads();
    s = 0.f; ss = 0.f;
#pragma unroll
    for (int i = 0; i < 8; i++) { s += sb[i]; ss += ssb[i]; }
    const float mean = s * (1.0f / DMODEL);
    const float var  = ss * (1.0f / DMODEL) - mean * mean;
    const float rstd = rsqrtf(var + 1e-5f);
    float4 gg = ((const float4*)g)[tid];
    float4 bb = ((const float4*)bta)[tid];
    float4 o;
    o.x = (v.x - mean) * rstd * gg.x + bb.x;
    o.y = (v.y - mean) * rstd * gg.y + bb.y;
    o.z = (v.z - mean) * rstd * gg.z + bb.z;
    o.w = (v.w - mean) * rstd * gg.w + bb.w;
    if (DUAL) ((float4*)(y2 + row * DMODEL))[tid] = o;
    float4 r;
    r.x = tf32r(o.x); r.y = tf32r(o.y); r.z = tf32r(o.z); r.w = tf32r(o.w);
    ((float4*)(y + row * DMODEL))[tid] = r;
}

// ---------------------------------------------------------------------------
// TF32 GEMM: C[M,N] = A[M,K] @ Wt[N,K]^T. Both operands [128][36] smem tiles,
// all fragments via ldmatrix.x4. 2-stage cp.async. Batched over gridDim.z.
// EPI: C = R + gelu_exact(..).  ROUND: tf32-round C on store.
// ---------------------------------------------------------------------------
__device__ __forceinline__ float gelu_exact(float x)
{
    return 0.5f * x * (1.0f + erff(x * 0.70710678118654752440f));
}

#define TS_STRIDE 36
#define G_TBUF (128 * TS_STRIDE)   // 4608 floats
#define G_SMEM_FLOATS (4 * G_TBUF)
#define G_SMEM_BYTES  (G_SMEM_FLOATS * 4)   // 73728

struct GemmBatch {
    const float* A[3];
    const float* B[3];   // transposed weights [N][K]
    float*       C[3];
    const float* R[3];
};

template <bool EPI, bool ROUND>
__global__ __launch_bounds__(256, 2) void gemm_tf32(GemmBatch gb, int M, int N, int K)
{
    extern __shared__ float sm[];
    float* As = sm;                  // [2][128][36]
    float* Bs = sm + 2 * G_TBUF;     // [2][128][36]

    const float* __restrict__ A  = gb.A[blockIdx.z];
    const float* __restrict__ Bt = gb.B[blockIdx.z];
    float* __restrict__ C        = gb.C[blockIdx.z];
    const float* __restrict__ R  = gb.R[blockIdx.z];

    const int tid  = threadIdx.x;
    const int lane = tid & 31;
    const int wid  = tid >> 5;
    const int grp  = lane >> 2;
    const int tig  = lane & 3;
    const int wm   = wid & 1;
    const int wn   = wid >> 1;
    const int bx   = blockIdx.x * 128;
    const int by   = blockIdx.y * 128;

    // A ldsm4 lane coords (16 rows x 8 cols)
    const int a_row = lane & 15;
    const int a_col = (lane >> 4) << 2;
    // B ldsm4 lane coords (rows n..n+7 @k0, n..n+7 @k0+4, n+8.. @k0, n+8.. @k0+4)
    const int b_row = (lane & 7) | ((lane & 16) >> 1);
    const int b_col = ((lane >> 3) & 1) << 2;

    const int lr = tid >> 3;          // 0..31
    const int lc = (tid & 7) << 2;

    float acc[4][4][4];
#pragma unroll
    for (int mt = 0; mt < 4; mt++)
#pragma unroll
        for (int nt = 0; nt < 4; nt++)
#pragma unroll
            for (int c = 0; c < 4; c++) acc[mt][nt][c] = 0.f;

    const int nk = K >> 5;

    // prologue: tile 0
    {
#pragma unroll
        for (int i = 0; i < 4; i++) {
            const int r = lr + i * 32;
            cpa16(&As[r * TS_STRIDE + lc], &A[(size_t)(by + r) * K + lc]);
            cpa16(&Bs[r * TS_STRIDE + lc], &Bt[(size_t)(bx + r) * K + lc]);
        }
        CP_COMMIT();
    }

    for (int t = 0; t < nk; t++) {
        const int cur = t & 1;
        if (t + 1 < nk) {
            const int nxt = cur ^ 1;
            const int k0 = (t + 1) << 5;
#pragma unroll
            for (int i = 0; i < 4; i++) {
                const int r = lr + i * 32;
                cpa16(&As[nxt * G_TBUF + r * TS_STRIDE + lc],
                      &A[(size_t)(by + r) * K + k0 + lc]);
                cpa16(&Bs[nxt * G_TBUF + r * TS_STRIDE + lc],
                      &Bt[(size_t)(bx + r) * K + k0 + lc]);
            }
            CP_COMMIT();
            CP_WAIT1();
        } else {
            CP_WAIT0();
        }
        __syncthreads();

        const float* Ab = As + cur * G_TBUF;
        const float* Bb = Bs + cur * G_TBUF;
#pragma unroll
        for (int ks = 0; ks < 4; ks++) {
            unsigned af[4][4];
#pragma unroll
            for (int mt = 0; mt < 4; mt++)
                ldsm4(af[mt], &Ab[(wm * 64 + mt * 16 + a_row) * TS_STRIDE + ks * 8 + a_col]);
            unsigned bt[2][4];
#pragma unroll
            for (int np = 0; np < 2; np++)
                ldsm4(bt[np], &Bb[(wn * 32 + np * 16 + b_row) * TS_STRIDE + ks * 8 + b_col]);
#pragma unroll
            for (int mt = 0; mt < 4; mt++)
#pragma unroll
                for (int nt = 0; nt < 4; nt++)
                    mma_tf32(acc[mt][nt], af[mt],
                             bt[nt >> 1][(nt & 1) * 2], bt[nt >> 1][(nt & 1) * 2 + 1]);
        }
        __syncthreads();
    }

    // epilogue
#pragma unroll
    for (int mt = 0; mt < 4; mt++) {
        const int r0 = by + wm * 64 + mt * 16 + grp;
#pragma unroll
        for (int nt = 0; nt < 4; nt++) {
            const int c0 = bx + wn * 32 + nt * 8 + tig * 2;
            const size_t i0 = (size_t)r0 * N + c0;
            const size_t i1 = (size_t)(r0 + 8) * N + c0;
            float2 o0 = make_float2(acc[mt][nt][0], acc[mt][nt][1]);
            float2 o1 = make_float2(acc[mt][nt][2], acc[mt][nt][3]);
            if (EPI) {
                float2 r0v = *(const float2*)&R[i0];
                float2 r1v = *(const float2*)&R[i1];
                o0.x = r0v.x + gelu_exact(o0.x);
                o0.y = r0v.y + gelu_exact(o0.y);
                o1.x = r1v.x + gelu_exact(o1.x);
                o1.y = r1v.y + gelu_exact(o1.y);
            }
            if (ROUND) {
                o0.x = tf32r(o0.x); o0.y = tf32r(o0.y);
                o1.x = tf32r(o1.x); o1.y = tf32r(o1.y);
            }
            *(float2*)&C[i0] = o0;
            *(float2*)&C[i1] = o1;
        }
    }
}

// ---------------------------------------------------------------------------
// Flash attention, TF32, pipelined (R5 structure). K-fragments via ldsm4.
// BM=128, BN=64, HD=128. 8 warps, warp-local softmax.
// ---------------------------------------------------------------------------
#define FA_QS 132
#define FA_KS 132
#define FA_VS 136
#define FA_PS 68
#define FA_KBUF (64 * FA_KS)
#define FA_Q_OFF 0
#define FA_K_OFF (128 * FA_QS)
#define FA_V_OFF (FA_K_OFF + 2 * FA_KBUF)
#define FA_P_OFF (FA_V_OFF + 64 * FA_VS)
#define FA_SMEM_FLOATS (FA_P_OFF + 128 * FA_PS)
#define FA_SMEM_BYTES  (FA_SMEM_FLOATS * 4)   // 204800

__global__ __launch_bounds__(256, 1) void flash_tc(const float* __restrict__ qg,
                                                   const float* __restrict__ kg,
                                                   const float* __restrict__ vg,
                                                   float* __restrict__ og)
{
    extern __shared__ float sm[];
    float* Qs = sm + FA_Q_OFF;
    float* Ks = sm + FA_K_OFF;   // [2][64][132]
    float* Vs = sm + FA_V_OFF;   // [64][136]
    float* Ps = sm + FA_P_OFF;   // [128][68]

    const int bh = blockIdx.y;
    const int b  = bh >> 3;
    const int h  = bh & 7;
    const int m0 = blockIdx.x * 128;
    const int tid  = threadIdx.x;
    const int lane = tid & 31;
    const int wid  = tid >> 5;
    const int grp  = lane >> 2;
    const int tig  = lane & 3;

    const int a_row = lane & 15;
    const int a_col = (lane >> 4) << 2;
    const int b_row = (lane & 7) | ((lane & 16) >> 1);
    const int b_col = ((lane >> 3) & 1) << 2;

    const size_t base = (size_t)b * SEQ * DMODEL + (size_t)h * HDIM;
    const float* qb = qg + base;
    const float* kb = kg + base;
    const float* vb = vg + base;

    const int ldr = tid >> 5;
    const int ldc = (tid & 31) << 2;

    // group 0: Q + K(0)
    {
#pragma unroll
        for (int i = 0; i < 16; i++)
            cpa16(&Qs[(ldr + i * 8) * FA_QS + ldc], &qb[(size_t)(m0 + ldr + i * 8) * DMODEL + ldc]);
#pragma unroll
        for (int i = 0; i < 8; i++)
            cpa16(&Ks[(ldr + i * 8) * FA_KS + ldc], &kb[(size_t)(ldr + i * 8) * DMODEL + ldc]);
        CP_COMMIT();
    }
    // group 1: V(0)
    {
#pragma unroll
        for (int i = 0; i < 8; i++)
            cpa16(&Vs[(ldr + i * 8) * FA_VS + ldc], &vb[(size_t)(ldr + i * 8) * DMODEL + ldc]);
        CP_COMMIT();
    }

    float mi[2] = {-1e30f, -1e30f};
    float li[2] = {0.f, 0.f};
    float oacc[16][4];
#pragma unroll
    for (int nt = 0; nt < 16; nt++)
#pragma unroll
        for (int c = 0; c < 4; c++) oacc[nt][c] = 0.f;

    const int NT = SEQ / 64;
    for (int t = 0; t < NT; t++) {
        const float* Kb = Ks + (t & 1) * FA_KBUF;

        CP_WAIT1();
        __syncthreads();

        // prefetch K(t+1)
        if (t + 1 < NT) {
            float* Kn = Ks + ((t + 1) & 1) * FA_KBUF;
            const size_t j1 = (size_t)(t + 1) * 64;
#pragma unroll
            for (int i = 0; i < 8; i++)
                cpa16(&Kn[(ldr + i * 8) * FA_KS + ldc], &kb[(j1 + ldr + i * 8) * DMODEL + ldc]);
            CP_COMMIT();
        }

        // ---- S = Q K^T : K-fragments via ldsm4 (2 n-tiles each) ----
        float s[8][4];
#pragma unroll
        for (int nt = 0; nt < 8; nt++)
#pragma unroll
            for (int c = 0; c < 4; c++) s[nt][c] = 0.f;

#pragma unroll
        for (int ks = 0; ks < 16; ks++) {
            unsigned af[4];
            ldsm4(af, &Qs[(wid * 16 + a_row) * FA_QS + ks * 8 + a_col]);
#pragma unroll
            for (int np = 0; np < 4; np++) {
                unsigned kt[4];
                ldsm4(kt, &Kb[(np * 16 + b_row) * FA_KS + ks * 8 + b_col]);
                mma_tf32(s[np * 2],     af, kt[0], kt[1]);
                mma_tf32(s[np * 2 + 1], af, kt[2], kt[3]);
            }
        }

        // ---- warp-local online softmax ----
        float mx0 = -1e30f, mx1 = -1e30f;
#pragma unroll
        for (int nt = 0; nt < 8; nt++) {
#pragma unroll
            for (int c = 0; c < 4; c++) {
                float x = s[nt][c] * SOFTMAX_SCALE;
                x = fminf(fmaxf(x, -10000.f), 10000.f);
                s[nt][c] = x;
            }
            mx0 = fmaxf(mx0, fmaxf(s[nt][0], s[nt][1]));
            mx1 = fmaxf(mx1, fmaxf(s[nt][2], s[nt][3]));
        }
        mx0 = fmaxf(mx0, __shfl_xor_sync(0xffffffffu, mx0, 1));
        mx0 = fmaxf(mx0, __shfl_xor_sync(0xffffffffu, mx0, 2));
        mx1 = fmaxf(mx1, __shfl_xor_sync(0xffffffffu, mx1, 1));
        mx1 = fmaxf(mx1, __shfl_xor_sync(0xffffffffu, mx1, 2));
        const float mn0 = fmaxf(mi[0], mx0);
        const float mn1 = fmaxf(mi[1], mx1);
        const float al0 = __expf(mi[0] - mn0);
        const float al1 = __expf(mi[1] - mn1);
        mi[0] = mn0; mi[1] = mn1;

        float sum0 = 0.f, sum1 = 0.f;
        const int prow = wid * 16 + grp;
#pragma unroll
        for (int nt = 0; nt < 8; nt++) {
            const float p0 = __expf(s[nt][0] - mn0);
            const float p1 = __expf(s[nt][1] - mn0);
            const float p2 = __expf(s[nt][2] - mn1);
            const float p3 = __expf(s[nt][3] - mn1);
            sum0 += p0 + p1;
            sum1 += p2 + p3;
            const int col = nt * 8 + tig * 2;
            *(float2*)&Ps[prow * FA_PS + col]       = make_float2(tf32r(p0), tf32r(p1));
            *(float2*)&Ps[(prow + 8) * FA_PS + col] = make_float2(tf32r(p2), tf32r(p3));
        }
        sum0 += __shfl_xor_sync(0xffffffffu, sum0, 1);
        sum0 += __shfl_xor_sync(0xffffffffu, sum0, 2);
        sum1 += __shfl_xor_sync(0xffffffffu, sum1, 1);
        sum1 += __shfl_xor_sync(0xffffffffu, sum1, 2);
        li[0] = li[0] * al0 + sum0;
        li[1] = li[1] * al1 + sum1;

#pragma unroll
        for (int nt = 0; nt < 16; nt++) {
            oacc[nt][0] *= al0; oacc[nt][1] *= al0;
            oacc[nt][2] *= al1; oacc[nt][3] *= al1;
        }

        // V(t) arrived
        CP_WAIT1();
        __syncthreads();

        // ---- O += P V ----
#pragma unroll
        for (int ks = 0; ks < 8; ks++) {
            unsigned af[4];
            ldsm4(af, &Ps[(wid * 16 + a_row) * FA_PS + ks * 8 + a_col]);
#pragma unroll
            for (int nt = 0; nt < 16; nt++) {
                const int nc = nt * 8 + grp;
                unsigned b0 = __float_as_uint(Vs[(ks * 8 + tig)     * FA_VS + nc]);
                unsigned b1 = __float_as_uint(Vs[(ks * 8 + tig + 4) * FA_VS + nc]);
                mma_tf32(oacc[nt], af, b0, b1);
            }
        }

        __syncthreads();
        if (t + 1 < NT) {
            const size_t j1 = (size_t)(t + 1) * 64;
#pragma unroll
            for (int i = 0; i < 8; i++)
                cpa16(&Vs[(ldr + i * 8) * FA_VS + ldc], &vb[(j1 + ldr + i * 8) * DMODEL + ldc]);
            CP_COMMIT();
        }
    }

    // write O
    const float i0 = 1.0f / li[0];
    const float i1 = 1.0f / li[1];
    const size_t row0 = (size_t)(b * SEQ + m0 + wid * 16 + grp);
#pragma unroll
    for (int nt = 0; nt < 16; nt++) {
        const int col = h * HDIM + nt * 8 + tig * 2;
        *(float2*)&og[row0 * DMODEL + col]       = make_float2(oacc[nt][0] * i0, oacc[nt][1] * i0);
        *(float2*)&og[(row0 + 8) * DMODEL + col] = make_float2(oacc[nt][2] * i1, oacc[nt][3] * i1);
    }
}

// ---------------------------------------------------------------------------
// Launch
// ---------------------------------------------------------------------------
extern "C" void kernel_launch(void* const* d_in, const int* in_sizes, int n_in,
                              void* d_out, int out_size)
{
    const float* Q     = (const float*)d_in[0];
    const float* Kin   = (const float*)d_in[1];
    const float* Vin   = (const float*)d_in[2];
    const float* Wq    = (const float*)d_in[3];
    const float* Wk    = (const float*)d_in[4];
    const float* Wv    = (const float*)d_in[5];
    const float* Wo    = (const float*)d_in[6];
    const float* pre_g = (const float*)d_in[7];
    const float* pre_b = (const float*)d_in[8];
    const float* ln_g  = (const float*)d_in[9];
    const float* ln_b  = (const float*)d_in[10];
    float* out = (float*)d_out;

    float *qn, *kn, *vr, *qq, *kk, *vv, *oo, *olnR, *olnF, *wt;
    cudaGetSymbolAddress((void**)&qn,   g_Qn);
    cudaGetSymbolAddress((void**)&kn,   g_Kn);
    cudaGetSymbolAddress((void**)&vr,   g_Vr);
    cudaGetSymbolAddress((void**)&qq,   g_q);
    cudaGetSymbolAddress((void**)&kk,   g_k);
    cudaGetSymbolAddress((void**)&vv,   g_v);
    cudaGetSymbolAddress((void**)&oo,   g_O);
    cudaGetSymbolAddress((void**)&olnR, g_OlnR);
    cudaGetSymbolAddress((void**)&olnF, g_OlnF);
    cudaGetSymbolAddress((void**)&wt,   g_Wt);

    cudaFuncSetAttribute(flash_tc,
                         cudaFuncAttributeMaxDynamicSharedMemorySize, FA_SMEM_BYTES);
    cudaFuncSetAttribute(gemm_tf32<false, true>,
                         cudaFuncAttributeMaxDynamicSharedMemorySize, G_SMEM_BYTES);
    cudaFuncSetAttribute(gemm_tf32<true, false>,
                         cudaFuncAttributeMaxDynamicSharedMemorySize, G_SMEM_BYTES);

    float* wq = wt;
    float* wk = wt + DMODEL * DMODEL;
    float* wv = wt + 2 * DMODEL * DMODEL;
    float* wo = wt + 3 * DMODEL * DMODEL;

    // 0) transpose+round weights (one launch) + round V input
    {
        WBatch wb;
        wb.src[0] = Wq; wb.dst[0] = wq;
        wb.src[1] = Wk; wb.dst[1] = wk;
        wb.src[2] = Wv; wb.dst[2] = wv;
        wb.src[3] = Wo; wb.dst[3] = wo;
        transpose_round_w<<<dim3(32, 32, 4), dim3(32, 8)>>>(wb);
    }
    round_tf32<<<NTOT / 4 / 256, 256>>>(Vin, vr, NTOT / 4);

    // 1) pre-LN on Q and K
    ln_kernel<false><<<MROWS, 256>>>(Q,   pre_g, pre_b, qn, nullptr);
    ln_kernel<false><<<MROWS, 256>>>(Kin, pre_g, pre_b, kn, nullptr);

    // 2) projections — single batched launch (gridDim.z = 3)
    {
        GemmBatch gb;
        gb.A[0] = qn;  gb.B[0] = wq; gb.C[0] = qq; gb.R[0] = nullptr;
        gb.A[1] = kn;  gb.B[1] = wk; gb.C[1] = kk; gb.R[1] = nullptr;
        gb.A[2] = vr;  gb.B[2] = wv; gb.C[2] = vv; gb.R[2] = nullptr;
        dim3 gg(DMODEL / 128, MROWS / 128, 3);
        gemm_tf32<false, true><<<gg, 256, G_SMEM_BYTES>>>(gb, MROWS, DMODEL, DMODEL);
    }

    // 3) attention
    flash_tc<<<dim3(SEQ / 128, BATCH * NHEAD), 256, FA_SMEM_BYTES>>>(qq, kk, vv, oo);

    // 4) post-LN (rounded + full)
    ln_kernel<true><<<MROWS, 256>>>(oo, ln_g, ln_b, olnR, olnF);

    // 5) output GEMM + gelu residual
    {
        GemmBatch gb;
        gb.A[0] = olnR; gb.B[0] = wo; gb.C[0] = out; gb.R[0] = olnF;
        gb.A[1] = gb.A[0]; gb.B[1] = gb.B[0]; gb.C[1] = gb.C[0]; gb.R[1] = gb.R[0];
        gb.A[2] = gb.A[0]; gb.B[2] = gb.B[0]; gb.C[2] = gb.C[0]; gb.R[2] = gb.R[0];
        dim3 gg(DMODEL / 128, MROWS / 128, 1);
        gemm_tf32<true, false><<<gg, 256, G_SMEM_BYTES>>>(gb, MROWS, DMODEL, DMODEL);
    }
}